// round 2
// baseline (speedup 1.0000x reference)
#include <cuda_runtime.h>
#include <cstdint>

#define CCH 256       // channels
#define TLEN 8192     // time
#define BSZ 4         // batch
#define TT 32         // time tile per block
#define NLAYER 10

// ---------------- device scratch (static, no allocation) ----------------
__device__ float g_wt[NLAYER * 3 * CCH * (2 * CCH)];   // [l][k][c][o]  (15.7 MB)
__device__ float g_wo[NLAYER * CCH * CCH];             // [l][c][o]     (2.6 MB)
__device__ float g_x[2 * (size_t)BSZ * CCH * TLEN];    // ping-pong x   (64 MB)

typedef unsigned long long u64;

__device__ __forceinline__ u64 pk2(float a, float b) {
    u64 r;
    asm("mov.b64 %0, {%1, %2};" : "=l"(r) : "f"(a), "f"(b));
    return r;
}
__device__ __forceinline__ u64 ffma2(u64 a, u64 b, u64 c) {
    u64 d;
    asm("fma.rn.f32x2 %0, %1, %2, %3;" : "=l"(d) : "l"(a), "l"(b), "l"(c));
    return d;
}
__device__ __forceinline__ float2 up2(u64 a) {
    float2 f;
    asm("mov.b64 {%0, %1}, %2;" : "=f"(f.x), "=f"(f.y) : "l"(a));
    return f;
}
__device__ __forceinline__ float sigf(float x) {
    return __fdividef(1.0f, 1.0f + __expf(-x));
}

// ---------------- weight transposes ----------------
// wconv: [L][2C][C][3]  ->  g_wt: [L][3][C][2C]
__global__ void transpose_conv_k(const float* __restrict__ w, float* __restrict__ wt) {
    const int total = NLAYER * (2 * CCH) * CCH * 3;
    for (int i = blockIdx.x * blockDim.x + threadIdx.x; i < total;
         i += gridDim.x * blockDim.x) {
        int k = i % 3;
        int c = (i / 3) % CCH;
        int o = (i / (3 * CCH)) % (2 * CCH);
        int l = i / (3 * CCH * 2 * CCH);
        wt[(((size_t)l * 3 + k) * CCH + c) * (2 * CCH) + o] = w[i];
    }
}
// wout: [L][C][C] (o,c) -> g_wo: [L][C][C] (c,o)
__global__ void transpose_out_k(const float* __restrict__ w, float* __restrict__ wt) {
    const int total = NLAYER * CCH * CCH;
    for (int i = blockIdx.x * blockDim.x + threadIdx.x; i < total;
         i += gridDim.x * blockDim.x) {
        int c = i % CCH;
        int o = (i / CCH) % CCH;
        int l = i / (CCH * CCH);
        wt[((size_t)l * CCH + c) * CCH + o] = w[i];
    }
}

// ---------------- fused layer kernel ----------------
// one block: batch b, time tile [t0, t0+32)
// phase1: load 3 shifted x tiles into smem
// phase2: z = conv (GEMM over k=3, c=256), packed f32x2 accum
// phase3: gate -> h; write skip; (last layer: write x_next = h + x)
// phase4: 1x1 out-proj + bias + residual -> x_next
__global__ __launch_bounds__(256, 1) void layer_kernel(
    const float* __restrict__ xin,
    float* __restrict__ xout,
    const float* __restrict__ wt,     // [3][C][2C]
    const float* __restrict__ bconv,  // [2C]
    const float* __restrict__ wot,    // [C][C]  (c-major)
    const float* __restrict__ bout,   // [C]
    float* __restrict__ skip,         // [B][C][T] slice of d_out
    int dil, int is_last)
{
    extern __shared__ float smem[];        // 3*C*TT = 24576 floats (96 KB)
    float* Xs  = smem;                     // Xs[k][c][tt] = smem[(k*C+c)*TT + tt]
    float* HsT = smem;                     // h, t-major [TT][257], overlaps Xs[0..1]

    const int tid = threadIdx.x;
    const int b   = blockIdx.y;
    const int t0  = blockIdx.x * TT;
    const float* xb = xin + (size_t)b * CCH * TLEN;

    // ---- phase 1: load shifted tiles (coalesced, 128B rows) ----
    for (int i = tid; i < 3 * CCH * TT; i += 256) {
        int k  = i >> 13;            // / (C*TT)
        int r  = i & 8191;
        int c  = r >> 5;
        int tt = r & 31;
        int ts = t0 + tt - dil * (2 - k);
        smem[i] = (ts >= 0) ? xb[c * TLEN + ts] : 0.0f;
    }
    __syncthreads();

    const int q     = tid & 63;
    const int ob    = q << 2;           // 4 consecutive output channels
    const int tbase = (tid >> 6) << 3;  // 8 consecutive t's

    // ---- phase 2: dilated conv GEMM ----
    u64 accT[16], accS[16];
    #pragma unroll
    for (int i = 0; i < 16; ++i) { accT[i] = 0ull; accS[i] = 0ull; }

    for (int c = 0; c < CCH; ++c) {
        #pragma unroll
        for (int k = 0; k < 3; ++k) {
            const float* xr = Xs + (((k << 8) + c) << 5) + tbase;
            u64 xv[4];
            xv[0] = *(const u64*)(xr);
            xv[1] = *(const u64*)(xr + 2);
            xv[2] = *(const u64*)(xr + 4);
            xv[3] = *(const u64*)(xr + 6);
            const float* wr = wt + ((size_t)(((k << 8) + c)) << 9) + ob;
            float4 wT = *(const float4*)wr;
            float4 wS = *(const float4*)(wr + CCH);
            float wTa[4] = {wT.x, wT.y, wT.z, wT.w};
            float wSa[4] = {wS.x, wS.y, wS.z, wS.w};
            #pragma unroll
            for (int oi = 0; oi < 4; ++oi) {
                u64 wp = pk2(wTa[oi], wTa[oi]);
                #pragma unroll
                for (int j = 0; j < 4; ++j)
                    accT[oi * 4 + j] = ffma2(wp, xv[j], accT[oi * 4 + j]);
                u64 ws = pk2(wSa[oi], wSa[oi]);
                #pragma unroll
                for (int j = 0; j < 4; ++j)
                    accS[oi * 4 + j] = ffma2(ws, xv[j], accS[oi * 4 + j]);
            }
        }
    }
    __syncthreads();   // everyone done reading Xs[0..1] before HsT overwrite

    // ---- phase 3: gate, skip write, (last layer residual) ----
    {
        float4 bT = *(const float4*)(bconv + ob);
        float4 bS = *(const float4*)(bconv + CCH + ob);
        float bTa[4] = {bT.x, bT.y, bT.z, bT.w};
        float bSa[4] = {bS.x, bS.y, bS.z, bS.w};
        #pragma unroll
        for (int oi = 0; oi < 4; ++oi) {
            int o = ob + oi;
            #pragma unroll
            for (int j = 0; j < 4; ++j) {
                int tt = tbase + 2 * j;
                float2 zt = up2(accT[oi * 4 + j]);
                float2 zs = up2(accS[oi * 4 + j]);
                float h0 = tanhf(zt.x + bTa[oi]) * sigf(zs.x + bSa[oi]);
                float h1 = tanhf(zt.y + bTa[oi]) * sigf(zs.y + bSa[oi]);
                float2 hv = make_float2(h0, h1);
                *(float2*)(skip + ((size_t)b * CCH + o) * TLEN + t0 + tt) = hv;
                if (is_last) {
                    const float2 xr = *(const float2*)(Xs + 2 * CCH * TT + o * TT + tt);
                    float2 ov = make_float2(h0 + xr.x, h1 + xr.y);
                    *(float2*)(xout + ((size_t)b * CCH + o) * TLEN + t0 + tt) = ov;
                } else {
                    HsT[tt * 257 + o]       = h0;
                    HsT[(tt + 1) * 257 + o] = h1;
                }
            }
        }
    }
    if (is_last) return;
    __syncthreads();

    // ---- phase 4: 1x1 out-proj + bias + residual ----
    {
        u64 acc[16];
        #pragma unroll
        for (int i = 0; i < 16; ++i) acc[i] = 0ull;

        for (int c = 0; c < CCH; ++c) {
            u64 hv[4];
            #pragma unroll
            for (int j = 0; j < 4; ++j) {
                int tt = tbase + 2 * j;
                hv[j] = pk2(HsT[tt * 257 + c], HsT[(tt + 1) * 257 + c]);
            }
            const float4 w4 = *(const float4*)(wot + (c << 8) + ob);
            float wa[4] = {w4.x, w4.y, w4.z, w4.w};
            #pragma unroll
            for (int oi = 0; oi < 4; ++oi) {
                u64 wp = pk2(wa[oi], wa[oi]);
                #pragma unroll
                for (int j = 0; j < 4; ++j)
                    acc[oi * 4 + j] = ffma2(wp, hv[j], acc[oi * 4 + j]);
            }
        }

        float4 bo = *(const float4*)(bout + ob);
        float boa[4] = {bo.x, bo.y, bo.z, bo.w};
        #pragma unroll
        for (int oi = 0; oi < 4; ++oi) {
            int o = ob + oi;
            #pragma unroll
            for (int j = 0; j < 4; ++j) {
                int tt = tbase + 2 * j;
                float2 v = up2(acc[oi * 4 + j]);
                const float2 xr = *(const float2*)(Xs + 2 * CCH * TT + o * TT + tt);
                v.x += boa[oi] + xr.x;
                v.y += boa[oi] + xr.y;
                *(float2*)(xout + ((size_t)b * CCH + o) * TLEN + t0 + tt) = v;
            }
        }
    }
}

// ---------------- host launcher ----------------
extern "C" void kernel_launch(void* const* d_in, const int* in_sizes, int n_in,
                              void* d_out, int out_size) {
    const float* input = (const float*)d_in[0];
    const float* wconv = (const float*)d_in[1];
    const float* bconv = (const float*)d_in[2];
    const float* wout  = (const float*)d_in[3];
    const float* bout  = (const float*)d_in[4];
    float* out = (float*)d_out;

    float *wt_d = nullptr, *wo_d = nullptr, *x_d = nullptr;
    cudaGetSymbolAddress((void**)&wt_d, g_wt);
    cudaGetSymbolAddress((void**)&wo_d, g_wo);
    cudaGetSymbolAddress((void**)&x_d,  g_x);

    cudaFuncSetAttribute(layer_kernel,
                         cudaFuncAttributeMaxDynamicSharedMemorySize, 98304);

    transpose_conv_k<<<2048, 256>>>(wconv, wt_d);
    transpose_out_k<<<512, 256>>>(wout, wo_d);

    const size_t XE = (size_t)BSZ * CCH * TLEN;   // 8388608
    const int DIL[NLAYER] = {1, 2, 4, 8, 16, 32, 64, 128, 256, 512};

    const float* xin = input;
    for (int l = 0; l < NLAYER; ++l) {
        float* xo   = (l == NLAYER - 1) ? out : (x_d + (size_t)(l & 1) * XE);
        float* skip = out + XE + (size_t)l * XE;
        dim3 grid(TLEN / TT, BSZ);
        layer_kernel<<<grid, 256, 98304>>>(
            xin, xo,
            wt_d + (size_t)l * 3 * CCH * 2 * CCH,
            bconv + l * 2 * CCH,
            wo_d + (size_t)l * CCH * CCH,
            bout + l * CCH,
            skip, DIL[l], (l == NLAYER - 1) ? 1 : 0);
        xin = xo;
    }
    (void)in_sizes; (void)n_in; (void)out_size;
}

// round 5
// speedup vs baseline: 2.8006x; 2.8006x over previous
#include <cuda_runtime.h>
#include <cuda_bf16.h>
#include <cstdint>

#define CCH 256
#define TLEN 8192
#define BSZ 4
#define NLAYER 10
#define STGB 81920     // per stage: W 64KB + X 16KB
#define SMEMB 163840   // 2 stages
typedef __nv_bfloat16 bf16;

// ---------- static scratch ----------
__device__ bf16 g_xh[(size_t)BSZ * TLEN * CCH];
__device__ bf16 g_xl[(size_t)BSZ * TLEN * CCH];
__device__ bf16 g_hh[(size_t)BSZ * TLEN * CCH];
__device__ bf16 g_hl[(size_t)BSZ * TLEN * CCH];
__device__ float g_xcm[(size_t)BSZ * CCH * TLEN];
__device__ bf16 g_wcA[(size_t)NLAYER * 2 * 12 * 2 * 16384];  // [l][g][chunk][half][256r][64k] swizzled
__device__ bf16 g_woA[(size_t)NLAYER * 4 * 2 * 16384];       // [l][chunk][half][256r][64k] swizzled

// ---------- helpers ----------
__device__ __forceinline__ uint32_t s2u(const void* p) {
    uint32_t a;
    asm("{ .reg .u64 t; cvta.to.shared.u64 t, %1; cvt.u32.u64 %0, t; }" : "=r"(a) : "l"(p));
    return a;
}
__device__ __forceinline__ void cpa16(uint32_t d, const void* s) {
    asm volatile("cp.async.cg.shared.global [%0], [%1], 16;" :: "r"(d), "l"(s));
}
__device__ __forceinline__ void cpa16z(uint32_t d, const void* s, uint32_t n) {
    asm volatile("cp.async.cg.shared.global [%0], [%1], 16, %2;" :: "r"(d), "l"(s), "r"(n));
}
#define CPC() asm volatile("cp.async.commit_group;" ::: "memory")
__device__ __forceinline__ uint32_t swz(uint32_t b) { return b ^ ((b >> 3) & 0x70); }
__device__ __forceinline__ float sigf(float x) {
    return __fdividef(1.0f, 1.0f + __expf(-x));
}
__device__ __forceinline__ void ldsm4(uint32_t& r0, uint32_t& r1, uint32_t& r2, uint32_t& r3, uint32_t a) {
    asm volatile("ldmatrix.sync.aligned.m8n8.x4.shared.b16 {%0,%1,%2,%3}, [%4];"
                 : "=r"(r0), "=r"(r1), "=r"(r2), "=r"(r3) : "r"(a));
}
__device__ __forceinline__ void mma_bf(float* c, const uint32_t* a, uint32_t b0, uint32_t b1) {
    asm volatile(
        "mma.sync.aligned.m16n8k16.row.col.f32.bf16.bf16.f32 "
        "{%0,%1,%2,%3},{%4,%5,%6,%7},{%8,%9},{%0,%1,%2,%3};"
        : "+f"(c[0]), "+f"(c[1]), "+f"(c[2]), "+f"(c[3])
        : "r"(a[0]), "r"(a[1]), "r"(a[2]), "r"(a[3]), "r"(b0), "r"(b1));
}

// ---------- prep kernels ----------
__global__ void prep_x(const float* __restrict__ in, bf16* __restrict__ xh, bf16* __restrict__ xl) {
    __shared__ float tl[32][33];
    int t0 = blockIdx.x * 32, c0 = blockIdx.y * 32, b = blockIdx.z;
    int tx = threadIdx.x, ty = threadIdx.y;
    #pragma unroll
    for (int r = 0; r < 4; ++r)
        tl[ty + r * 8][tx] = in[((size_t)b * CCH + c0 + ty + r * 8) * TLEN + t0 + tx];
    __syncthreads();
    #pragma unroll
    for (int r = 0; r < 4; ++r) {
        int t = t0 + ty + r * 8;
        float v = tl[tx][ty + r * 8];
        bf16 hi = __float2bfloat16(v);
        size_t o = ((size_t)b * TLEN + t) * CCH + c0 + tx;
        xh[o] = hi; xl[o] = __float2bfloat16(v - __bfloat162float(hi));
    }
}

__global__ void prep_wc(const float* __restrict__ w, bf16* __restrict__ wa) {
    size_t i = (size_t)blockIdx.x * 256 + threadIdx.x;
    if (i >= (size_t)NLAYER * 2 * 12 * 2 * 16384) return;
    int e = (int)(i & 16383);
    int tile = (int)(i >> 14);
    int half = tile & 1;
    int chunk = (tile >> 1) % 12;
    int lg = (tile >> 1) / 12;
    int g = lg & 1, l = lg >> 1;
    int row = e >> 6, k = e & 63;
    int o = (row < 128) ? g * 128 + row : 128 + g * 128 + row;
    int tap = chunk >> 2;
    int c = (chunk & 3) * 64 + k;
    float v = w[(((size_t)l * 512 + o) * 256 + c) * 3 + tap];
    bf16 hi = __float2bfloat16(v);
    bf16 val = half ? __float2bfloat16(v - __bfloat162float(hi)) : hi;
    wa[(size_t)tile * 16384 + (swz(row * 128 + k * 2) >> 1)] = val;
}

__global__ void prep_wo(const float* __restrict__ w, bf16* __restrict__ wa) {
    size_t i = (size_t)blockIdx.x * 256 + threadIdx.x;
    if (i >= (size_t)NLAYER * 4 * 2 * 16384) return;
    int e = (int)(i & 16383);
    int tile = (int)(i >> 14);
    int half = tile & 1;
    int chunk = (tile >> 1) & 3;
    int l = (tile >> 1) >> 2;
    int row = e >> 6, k = e & 63;
    int c = chunk * 64 + k;
    float v = w[((size_t)l * 256 + row) * 256 + c];
    bf16 hi = __float2bfloat16(v);
    bf16 val = half ? __float2bfloat16(v - __bfloat162float(hi)) : hi;
    wa[(size_t)tile * 16384 + (swz(row * 128 + k * 2) >> 1)] = val;
}

// ---------- main-loop compute (shared by both kernels) ----------
__device__ __forceinline__ void compute_stage(
    uint32_t Wb, uint32_t Xb, int tg, int oq, int lane, float acc[2][8][4])
{
    #pragma unroll
    for (int kk = 0; kk < 4; ++kk) {
        uint32_t Ahf[2][4], Alf[2][4];
        int ar = tg * 32 + (lane & 15);
        int aseg = 2 * kk + (lane >> 4);
        #pragma unroll
        for (int mt = 0; mt < 2; ++mt) {
            int r = ar + mt * 16;
            uint32_t aa = Xb + r * 128 + ((uint32_t)(aseg ^ (r & 7)) << 4);
            ldsm4(Ahf[mt][0], Ahf[mt][1], Ahf[mt][2], Ahf[mt][3], aa);
            ldsm4(Alf[mt][0], Alf[mt][1], Alf[mt][2], Alf[mt][3], aa + 8192);
        }
        #pragma unroll
        for (int np = 0; np < 4; ++np) {
            int br = oq * 64 + np * 16 + ((lane >> 4) << 3) + (lane & 7);
            int bseg = 2 * kk + ((lane >> 3) & 1);
            uint32_t ba = Wb + br * 128 + ((uint32_t)(bseg ^ (br & 7)) << 4);
            uint32_t bh0, bh1, bh2, bh3, bl0, bl1, bl2, bl3;
            ldsm4(bh0, bh1, bh2, bh3, ba);
            ldsm4(bl0, bl1, bl2, bl3, ba + 32768);
            #pragma unroll
            for (int mt = 0; mt < 2; ++mt) {
                mma_bf(acc[mt][2 * np],     Ahf[mt], bh0, bh1);
                mma_bf(acc[mt][2 * np + 1], Ahf[mt], bh2, bh3);
                mma_bf(acc[mt][2 * np],     Alf[mt], bh0, bh1);
                mma_bf(acc[mt][2 * np + 1], Alf[mt], bh2, bh3);
                mma_bf(acc[mt][2 * np],     Ahf[mt], bl0, bl1);
                mma_bf(acc[mt][2 * np + 1], Ahf[mt], bl2, bl3);
            }
        }
    }
}

// ---------- conv layer kernel ----------
__global__ __launch_bounds__(256, 1) void conv_k(
    const bf16* __restrict__ xh, const bf16* __restrict__ xl,
    const bf16* __restrict__ wA, const float* __restrict__ bconv,
    const float* __restrict__ xres, float* __restrict__ skip,
    bf16* __restrict__ hh, bf16* __restrict__ hl,
    float* __restrict__ xout, int dil, int last)
{
    extern __shared__ char sm[];
    uint32_t sbd = s2u(sm);
    int tid = threadIdx.x, lane = tid & 31, wid = tid >> 5;
    int g = blockIdx.y;
    int b = blockIdx.x >> 7, t0 = (blockIdx.x & 127) << 6;
    int tg = wid & 1, oq = wid >> 1;
    const char* xhB = (const char*)xh;
    const char* xlB = (const char*)xl;

    auto load_chunk = [&](int c, int s) {
        uint32_t SS = sbd + s * STGB;
        // FIX: weight tiles are [g][chunk] within the layer
        const char* wsrc = (const char*)(wA + ((size_t)(g * 12 + c)) * 32768);
        #pragma unroll
        for (int it = 0; it < 16; ++it) {
            uint32_t off = it * 4096 + tid * 16;
            cpa16(SS + off, wsrc + off);
        }
        int tap = c >> 2, cq = c & 3;
        int tt = tid >> 2, sg0 = (tid & 3) * 2;
        int ts = t0 + tt - dil * (2 - tap);
        uint32_t pr = ts >= 0 ? 16u : 0u;
        size_t gb = (size_t)(b * TLEN + (ts < 0 ? 0 : ts)) * 512 + cq * 128;
        #pragma unroll
        for (int j = 0; j < 2; ++j) {
            int sg = sg0 + j;
            uint32_t dst = SS + 65536 + tt * 128 + ((uint32_t)(sg ^ (tt & 7)) << 4);
            cpa16z(dst, xhB + gb + sg * 16, pr);
            cpa16z(dst + 8192, xlB + gb + sg * 16, pr);
        }
        CPC();
    };

    float acc[2][8][4];
    #pragma unroll
    for (int a = 0; a < 2; ++a)
        #pragma unroll
        for (int n = 0; n < 8; ++n)
            #pragma unroll
            for (int q = 0; q < 4; ++q) acc[a][n][q] = 0.0f;

    load_chunk(0, 0);
    load_chunk(1, 1);
    for (int c = 0; c < 12; ++c) {
        int s = c & 1;
        if (c < 11) asm volatile("cp.async.wait_group 1;" ::: "memory");
        else        asm volatile("cp.async.wait_group 0;" ::: "memory");
        __syncthreads();
        compute_stage(sbd + s * STGB, sbd + s * STGB + 65536, tg, oq, lane, acc);
        __syncthreads();
        if (c + 2 < 12) load_chunk(c + 2, s);
    }

    // ---- epilogue ----
    float* zb = (float*)sm;
    #pragma unroll
    for (int mt = 0; mt < 2; ++mt)
        #pragma unroll
        for (int nt = 0; nt < 8; ++nt) {
            int t = tg * 32 + mt * 16 + (lane >> 2);
            int o = oq * 64 + nt * 8 + (lane & 3) * 2;
            *(float2*)&zb[t * 260 + o]       = make_float2(acc[mt][nt][0], acc[mt][nt][1]);
            *(float2*)&zb[(t + 8) * 260 + o] = make_float2(acc[mt][nt][2], acc[mt][nt][3]);
        }
    __syncthreads();
    // gating in place (cols 0-127 tanh, 128-255 sig)
    for (int i = tid; i < 64 * 32; i += 256) {
        int t = i >> 5, c0 = (i & 31) * 4;
        #pragma unroll
        for (int j = 0; j < 4; ++j) {
            float zt = zb[t * 260 + c0 + j];
            float zs = zb[t * 260 + 128 + c0 + j];
            float h = tanhf(zt + bconv[g * 128 + c0 + j]) *
                      sigf(zs + bconv[256 + g * 128 + c0 + j]);
            zb[t * 260 + c0 + j] = h;
        }
    }
    __syncthreads();
    // skip write (c-major) + last-layer residual output
    for (int i = tid; i < 128 * 16; i += 256) {
        int o = i >> 4, sg = i & 15, t = sg * 4;
        float4 v;
        v.x = zb[(t + 0) * 260 + o];
        v.y = zb[(t + 1) * 260 + o];
        v.z = zb[(t + 2) * 260 + o];
        v.w = zb[(t + 3) * 260 + o];
        size_t go = ((size_t)(b * 256) + g * 128 + o) * TLEN + t0 + t;
        *(float4*)(skip + go) = v;
        if (last) {
            float4 xr = *(const float4*)(xres + go);
            float4 ov = make_float4(v.x + xr.x, v.y + xr.y, v.z + xr.z, v.w + xr.w);
            *(float4*)(xout + go) = ov;
        }
    }
    if (!last) {
        for (int i = tid; i < 64 * 32; i += 256) {
            int t = i >> 5, c0 = (i & 31) * 4;
            float v0 = zb[t * 260 + c0], v1 = zb[t * 260 + c0 + 1];
            float v2 = zb[t * 260 + c0 + 2], v3 = zb[t * 260 + c0 + 3];
            bf16 h0 = __float2bfloat16(v0), h1 = __float2bfloat16(v1);
            bf16 h2 = __float2bfloat16(v2), h3 = __float2bfloat16(v3);
            size_t gi = ((size_t)(b * TLEN) + t0 + t) * CCH + g * 128 + c0;
            ((__nv_bfloat162*)(hh + gi))[0] = __nv_bfloat162(h0, h1);
            ((__nv_bfloat162*)(hh + gi))[1] = __nv_bfloat162(h2, h3);
            bf16 l0 = __float2bfloat16(v0 - __bfloat162float(h0));
            bf16 l1 = __float2bfloat16(v1 - __bfloat162float(h1));
            bf16 l2 = __float2bfloat16(v2 - __bfloat162float(h2));
            bf16 l3 = __float2bfloat16(v3 - __bfloat162float(h3));
            ((__nv_bfloat162*)(hl + gi))[0] = __nv_bfloat162(l0, l1);
            ((__nv_bfloat162*)(hl + gi))[1] = __nv_bfloat162(l2, l3);
        }
    }
}

// ---------- 1x1 + residual layer ----------
__global__ __launch_bounds__(256, 1) void out_k(
    const bf16* __restrict__ hh, const bf16* __restrict__ hl,
    const bf16* __restrict__ wA, const float* __restrict__ bout,
    const float* __restrict__ xres, float* __restrict__ xcm,
    bf16* __restrict__ xh, bf16* __restrict__ xl)
{
    extern __shared__ char sm[];
    uint32_t sbd = s2u(sm);
    int tid = threadIdx.x, lane = tid & 31, wid = tid >> 5;
    int b = blockIdx.x >> 7, t0 = (blockIdx.x & 127) << 6;
    int tg = wid & 1, oq = wid >> 1;
    const char* hhB = (const char*)hh;
    const char* hlB = (const char*)hl;

    auto load_chunk = [&](int c, int s) {
        uint32_t SS = sbd + s * STGB;
        const char* wsrc = (const char*)(wA + (size_t)c * 32768);
        #pragma unroll
        for (int it = 0; it < 16; ++it) {
            uint32_t off = it * 4096 + tid * 16;
            cpa16(SS + off, wsrc + off);
        }
        int tt = tid >> 2, sg0 = (tid & 3) * 2;
        size_t gb = (size_t)(b * TLEN + t0 + tt) * 512 + c * 128;
        #pragma unroll
        for (int j = 0; j < 2; ++j) {
            int sg = sg0 + j;
            uint32_t dst = SS + 65536 + tt * 128 + ((uint32_t)(sg ^ (tt & 7)) << 4);
            cpa16(dst, hhB + gb + sg * 16);
            cpa16(dst + 8192, hlB + gb + sg * 16);
        }
        CPC();
    };

    float acc[2][8][4];
    #pragma unroll
    for (int a = 0; a < 2; ++a)
        #pragma unroll
        for (int n = 0; n < 8; ++n)
            #pragma unroll
            for (int q = 0; q < 4; ++q) acc[a][n][q] = 0.0f;

    load_chunk(0, 0);
    load_chunk(1, 1);
    for (int c = 0; c < 4; ++c) {
        int s = c & 1;
        if (c < 3) asm volatile("cp.async.wait_group 1;" ::: "memory");
        else       asm volatile("cp.async.wait_group 0;" ::: "memory");
        __syncthreads();
        compute_stage(sbd + s * STGB, sbd + s * STGB + 65536, tg, oq, lane, acc);
        __syncthreads();
        if (c + 2 < 4) load_chunk(c + 2, s);
    }

    float* zb = (float*)sm;
    #pragma unroll
    for (int mt = 0; mt < 2; ++mt)
        #pragma unroll
        for (int nt = 0; nt < 8; ++nt) {
            int t = tg * 32 + mt * 16 + (lane >> 2);
            int o = oq * 64 + nt * 8 + (lane & 3) * 2;
            *(float2*)&zb[t * 260 + o]       = make_float2(acc[mt][nt][0], acc[mt][nt][1]);
            *(float2*)&zb[(t + 8) * 260 + o] = make_float2(acc[mt][nt][2], acc[mt][nt][3]);
        }
    __syncthreads();
    // bias + residual -> xcm (c-major) and back into zbuf
    for (int i = tid; i < 256 * 16; i += 256) {
        int o = i >> 4, sg = i & 15, t = sg * 4;
        size_t go = ((size_t)(b * 256) + o) * TLEN + t0 + t;
        float4 xr = *(const float4*)(xres + go);
        float bo = bout[o];
        float4 v;
        v.x = zb[(t + 0) * 260 + o] + bo + xr.x;
        v.y = zb[(t + 1) * 260 + o] + bo + xr.y;
        v.z = zb[(t + 2) * 260 + o] + bo + xr.z;
        v.w = zb[(t + 3) * 260 + o] + bo + xr.w;
        *(float4*)(xcm + go) = v;
        zb[(t + 0) * 260 + o] = v.x;
        zb[(t + 1) * 260 + o] = v.y;
        zb[(t + 2) * 260 + o] = v.z;
        zb[(t + 3) * 260 + o] = v.w;
    }
    __syncthreads();
    // t-major bf16 hi/lo for next layer
    for (int i = tid; i < 64 * 64; i += 256) {
        int t = i >> 6, c0 = (i & 63) * 4;
        float v0 = zb[t * 260 + c0], v1 = zb[t * 260 + c0 + 1];
        float v2 = zb[t * 260 + c0 + 2], v3 = zb[t * 260 + c0 + 3];
        bf16 h0 = __float2bfloat16(v0), h1 = __float2bfloat16(v1);
        bf16 h2 = __float2bfloat16(v2), h3 = __float2bfloat16(v3);
        size_t gi = ((size_t)(b * TLEN) + t0 + t) * CCH + c0;
        ((__nv_bfloat162*)(xh + gi))[0] = __nv_bfloat162(h0, h1);
        ((__nv_bfloat162*)(xh + gi))[1] = __nv_bfloat162(h2, h3);
        bf16 l0 = __float2bfloat16(v0 - __bfloat162float(h0));
        bf16 l1 = __float2bfloat16(v1 - __bfloat162float(h1));
        bf16 l2 = __float2bfloat16(v2 - __bfloat162float(h2));
        bf16 l3 = __float2bfloat16(v3 - __bfloat162float(h3));
        ((__nv_bfloat162*)(xl + gi))[0] = __nv_bfloat162(l0, l1);
        ((__nv_bfloat162*)(xl + gi))[1] = __nv_bfloat162(l2, l3);
    }
}

// ---------- host ----------
extern "C" void kernel_launch(void* const* d_in, const int* in_sizes, int n_in,
                              void* d_out, int out_size) {
    const float* input = (const float*)d_in[0];
    const float* wconv = (const float*)d_in[1];
    const float* bconv = (const float*)d_in[2];
    const float* wout  = (const float*)d_in[3];
    const float* bout  = (const float*)d_in[4];
    float* out = (float*)d_out;

    bf16 *xh, *xl, *hh, *hl, *wcA, *woA; float* xcm;
    cudaGetSymbolAddress((void**)&xh, g_xh);
    cudaGetSymbolAddress((void**)&xl, g_xl);
    cudaGetSymbolAddress((void**)&hh, g_hh);
    cudaGetSymbolAddress((void**)&hl, g_hl);
    cudaGetSymbolAddress((void**)&xcm, g_xcm);
    cudaGetSymbolAddress((void**)&wcA, g_wcA);
    cudaGetSymbolAddress((void**)&woA, g_woA);

    cudaFuncSetAttribute(conv_k, cudaFuncAttributeMaxDynamicSharedMemorySize, SMEMB);
    cudaFuncSetAttribute(out_k,  cudaFuncAttributeMaxDynamicSharedMemorySize, SMEMB);

    prep_x<<<dim3(TLEN / 32, CCH / 32, BSZ), dim3(32, 8)>>>(input, xh, xl);
    {
        size_t n = (size_t)NLAYER * 2 * 12 * 2 * 16384;
        prep_wc<<<(unsigned)((n + 255) / 256), 256>>>(wconv, wcA);
    }
    {
        size_t n = (size_t)NLAYER * 4 * 2 * 16384;
        prep_wo<<<(unsigned)((n + 255) / 256), 256>>>(wout, woA);
    }

    const size_t XE = (size_t)BSZ * CCH * TLEN;
    const int DIL[NLAYER] = {1, 2, 4, 8, 16, 32, 64, 128, 256, 512};

    for (int l = 0; l < NLAYER; ++l) {
        int last = (l == NLAYER - 1);
        conv_k<<<dim3(512, 2), 256, SMEMB>>>(
            xh, xl, wcA + (size_t)l * 2 * 12 * 2 * 16384, bconv + l * 512,
            xcm, out + XE + (size_t)l * XE, hh, hl, out, DIL[l], last);
        if (!last) {
            out_k<<<512, 256, SMEMB>>>(
                hh, hl, woA + (size_t)l * 4 * 2 * 16384, bout + l * 256,
                (l == 0) ? input : xcm, xcm, xh, xl);
        }
    }
    (void)in_sizes; (void)n_in; (void)out_size;
}